// round 5
// baseline (speedup 1.0000x reference)
#include <cuda_runtime.h>
#include <cstdint>

namespace {

// smem word offsets
constexpr int QH = 0;       // Q hi tf32, stride 36, 64 rows
constexpr int QL = 2304;    // Q lo
constexpr int KH = 4608;    // K hi
constexpr int KL = 6912;    // K lo
constexpr int VT = 9216;    // V transposed [chan][tok], stride 68, 32 rows
constexpr int BI = 11392;   // bias, 225 floats
constexpr int SMW = 11620;  // 46480 bytes
constexpr int PO = 0;       // P overlays QH/QL, stride 68, 64 rows (4352 < 4608)

__device__ __forceinline__ uint32_t cvt_tf32(float x) {
    uint32_t u;
    asm("cvt.rna.tf32.f32 %0, %1;" : "=r"(u) : "f"(x));
    return u;
}
__device__ __forceinline__ uint32_t smem_u32(const void* p) {
    uint32_t a;
    asm("{ .reg .u64 t; cvta.to.shared.u64 t, %1; cvt.u32.u64 %0, t; }" : "=r"(a) : "l"(p));
    return a;
}
__device__ __forceinline__ void mma8(float* c, const uint32_t* a, uint32_t b0, uint32_t b1) {
    asm volatile("mma.sync.aligned.m16n8k8.row.col.f32.tf32.tf32.f32 "
        "{%0,%1,%2,%3}, {%4,%5,%6,%7}, {%8,%9}, {%0,%1,%2,%3};"
        : "+f"(c[0]), "+f"(c[1]), "+f"(c[2]), "+f"(c[3])
        : "r"(a[0]), "r"(a[1]), "r"(a[2]), "r"(a[3]), "r"(b0), "r"(b1));
}
__device__ __forceinline__ void ldsm4(uint32_t* r, uint32_t addr) {
    asm volatile("ldmatrix.sync.aligned.m8n8.x4.shared.b16 {%0,%1,%2,%3}, [%4];"
        : "=r"(r[0]), "=r"(r[1]), "=r"(r[2]), "=r"(r[3]) : "r"(addr));
}

__global__ __launch_bounds__(128, 4)
void swin_mma_kernel(const float* __restrict__ gq, const float* __restrict__ gk,
                     const float* __restrict__ gv, const float* __restrict__ gbias,
                     float* __restrict__ gout)
{
    __shared__ uint32_t SM[SMW];

    const int tid   = threadIdx.x;
    const int head  = blockIdx.x & 15;
    const int wy    = blockIdx.x >> 4;
    const int b     = wy >> 6;
    const int win   = wy & 63;
    const int win_h = win >> 3, win_w = win & 7;
    const float scale = 0.17677669529663687f;   // 1/sqrt(32)

    // ---- load Q,K,V (gather applies cyclic shift -4); tf32 hi/lo split; V transposed ----
    #pragma unroll
    for (int r = 0; r < 4; ++r) {
        int u = tid + (r << 7);               // 0..511
        int t = u >> 3;                       // token
        int cq = u & 7;                       // channel quad
        int sh  = ((win_h << 3) + (t >> 3) + 4) & 63;
        int sw2 = ((win_w << 3) + (t & 7) + 4) & 63;
        int gbase = ((((b << 6) + sh) << 6) + sw2) * 512 + head * 32 + (cq << 2);
        float4 q = *reinterpret_cast<const float4*>(gq + gbase);
        float4 k = *reinterpret_cast<const float4*>(gk + gbase);
        float4 v = *reinterpret_cast<const float4*>(gv + gbase);
        q.x *= scale; q.y *= scale; q.z *= scale; q.w *= scale;
        uint4 qh, ql, kh, kl;
        qh.x = cvt_tf32(q.x); ql.x = cvt_tf32(q.x - __uint_as_float(qh.x));
        qh.y = cvt_tf32(q.y); ql.y = cvt_tf32(q.y - __uint_as_float(qh.y));
        qh.z = cvt_tf32(q.z); ql.z = cvt_tf32(q.z - __uint_as_float(qh.z));
        qh.w = cvt_tf32(q.w); ql.w = cvt_tf32(q.w - __uint_as_float(qh.w));
        kh.x = cvt_tf32(k.x); kl.x = cvt_tf32(k.x - __uint_as_float(kh.x));
        kh.y = cvt_tf32(k.y); kl.y = cvt_tf32(k.y - __uint_as_float(kh.y));
        kh.z = cvt_tf32(k.z); kl.z = cvt_tf32(k.z - __uint_as_float(kh.z));
        kh.w = cvt_tf32(k.w); kl.w = cvt_tf32(k.w - __uint_as_float(kh.w));
        int o36 = t * 36 + (cq << 2);
        *reinterpret_cast<uint4*>(&SM[QH + o36]) = qh;
        *reinterpret_cast<uint4*>(&SM[QL + o36]) = ql;
        *reinterpret_cast<uint4*>(&SM[KH + o36]) = kh;
        *reinterpret_cast<uint4*>(&SM[KL + o36]) = kl;
        int c0 = cq << 2;
        SM[VT + (c0 + 0) * 68 + t] = cvt_tf32(v.x);
        SM[VT + (c0 + 1) * 68 + t] = cvt_tf32(v.y);
        SM[VT + (c0 + 2) * 68 + t] = cvt_tf32(v.z);
        SM[VT + (c0 + 3) * 68 + t] = cvt_tf32(v.w);
    }
    for (int t = tid; t < 225; t += 128)
        reinterpret_cast<float*>(SM)[BI + t] = gbias[t * 16 + head];
    __syncthreads();

    const int w    = tid >> 5;
    const int lane = tid & 31;
    const int g    = lane >> 2;
    const int t4   = lane & 3;
    const int mi   = lane >> 3;     // matrix index 0..3 for ldmatrix
    const int l7   = lane & 7;
    const int m0   = w << 4;
    const int iA   = m0 + g;
    const int iB   = m0 + g + 8;

    const uint32_t smb = smem_u32(SM);
    // A-frag addr (Q): matrix mi -> rows m0 + (mi&1)*8, col block (mi>>1)*4
    const uint32_t aRow = (uint32_t)(m0 + ((mi & 1) << 3) + l7);
    const uint32_t aQHb = smb + ((QH + aRow * 36 + ((mi >> 1) << 2)) << 2);
    const uint32_t aQLb = aQHb + (uint32_t)((QL - QH) << 2);
    // B-frag addr (K): matrix mi -> n-tile (2m + (mi>>1)), col block (mi&1)*4
    uint32_t bKHb[4], bKLb[4];
    #pragma unroll
    for (int m = 0; m < 4; ++m) {
        uint32_t row = (uint32_t)((((m << 1) + (mi >> 1)) << 3) + l7);
        bKHb[m] = smb + ((KH + row * 36 + ((mi & 1) << 2)) << 2);
        bKLb[m] = bKHb[m] + (uint32_t)((KL - KH) << 2);
    }

    // ---- QK: 3xTF32 (qh*kh + ql*kh + qh*kl), LDSM-fed ----
    float c[8][4] = {};
    #pragma unroll
    for (int ks = 0; ks < 4; ++ks) {
        uint32_t ah[4], al[4];
        ldsm4(ah, aQHb + ks * 32u);
        ldsm4(al, aQLb + ks * 32u);
        #pragma unroll
        for (int m = 0; m < 4; ++m) {
            uint32_t bh[4], bl[4];
            ldsm4(bh, bKHb[m] + ks * 32u);
            ldsm4(bl, bKLb[m] + ks * 32u);
            float* c0 = c[2 * m];
            float* c1 = c[2 * m + 1];
            mma8(c0, ah, bh[0], bh[1]);
            mma8(c0, al, bh[0], bh[1]);
            mma8(c0, ah, bl[0], bl[1]);
            mma8(c1, ah, bh[2], bh[3]);
            mma8(c1, al, bh[2], bh[3]);
            mma8(c1, ah, bl[2], bl[3]);
        }
    }
    __syncthreads();   // Q/K reads done; QH/QL region free for P overlay

    // ---- epilogue: bias + analytic shift-mask + softmax ----
    const float* bias = reinterpret_cast<const float*>(SM) + BI;
    const bool wh7 = (win_h == 7), ww7 = (win_w == 7);
    const bool hA4 = ((iA >> 3) >= 4), hB4 = ((iB >> 3) >= 4);
    const bool wA4 = ((iA & 7) >= 4),  wB4 = ((iB & 7) >= 4);
    const bool jw4 = (t4 >= 2);
    const int bA = 15 * (iA >> 3) + (iA & 7) + 112;
    const int bB = 15 * (iB >> 3) + (iB & 7) + 112;

    float mA = -1e30f, mB = -1e30f;
    #pragma unroll
    for (int nt = 0; nt < 8; ++nt) {
        const bool jh4 = (nt >= 4);
        const float subA = ((wh7 && (hA4 != jh4)) || (ww7 && (wA4 != jw4))) ? 100.0f : 0.0f;
        const float subB = ((wh7 && (hB4 != jh4)) || (ww7 && (wB4 != jw4))) ? 100.0f : 0.0f;
        #pragma unroll
        for (int q = 0; q < 2; ++q) {
            int bj = 15 * nt + (t4 << 1) + q;
            float xA = c[nt][q]     + bias[bA - bj] - subA;
            float xB = c[nt][2 + q] + bias[bB - bj] - subB;
            c[nt][q] = xA; c[nt][2 + q] = xB;
            mA = fmaxf(mA, xA); mB = fmaxf(mB, xB);
        }
    }
    mA = fmaxf(mA, __shfl_xor_sync(0xffffffffu, mA, 1));
    mA = fmaxf(mA, __shfl_xor_sync(0xffffffffu, mA, 2));
    mB = fmaxf(mB, __shfl_xor_sync(0xffffffffu, mB, 1));
    mB = fmaxf(mB, __shfl_xor_sync(0xffffffffu, mB, 2));
    float sA = 0.0f, sB = 0.0f;
    #pragma unroll
    for (int nt = 0; nt < 8; ++nt) {
        #pragma unroll
        for (int q = 0; q < 2; ++q) {
            float pA = __expf(c[nt][q] - mA);
            float pB = __expf(c[nt][2 + q] - mB);
            c[nt][q] = pA; c[nt][2 + q] = pB;
            sA += pA; sB += pB;
        }
    }
    sA += __shfl_xor_sync(0xffffffffu, sA, 1);
    sA += __shfl_xor_sync(0xffffffffu, sA, 2);
    sB += __shfl_xor_sync(0xffffffffu, sB, 1);
    sB += __shfl_xor_sync(0xffffffffu, sB, 2);
    const float invA = 1.0f / sA, invB = 1.0f / sB;

    // normalized P (tf32) -> smem, stride 68
    #pragma unroll
    for (int nt = 0; nt < 8; ++nt) {
        int jc = (nt << 3) + (t4 << 1);
        uint2 pa, pb;
        pa.x = cvt_tf32(c[nt][0] * invA); pa.y = cvt_tf32(c[nt][1] * invA);
        pb.x = cvt_tf32(c[nt][2] * invB); pb.y = cvt_tf32(c[nt][3] * invB);
        *reinterpret_cast<uint2*>(&SM[PO + iA * 68 + jc]) = pa;
        *reinterpret_cast<uint2*>(&SM[PO + iB * 68 + jc]) = pb;
    }
    __syncwarp();

    // ---- PV: O = P @ V, LDSM-fed (one x4 covers 2 k-steps of Vt) ----
    const uint32_t aPb = smb + ((PO + aRow * 68 + ((mi >> 1) << 2)) << 2);
    float o[4][4] = {};
    #pragma unroll
    for (int kp = 0; kp < 4; ++kp) {          // k-step pairs: ks = 2kp, 2kp+1
        uint32_t a0[4], a1[4];
        ldsm4(a0, aPb + (2 * kp) * 32u);
        ldsm4(a1, aPb + (2 * kp + 1) * 32u);
        #pragma unroll
        for (int nt = 0; nt < 4; ++nt) {
            uint32_t bv[4];
            uint32_t addr = smb + ((VT + ((nt << 3) + l7) * 68 + (kp << 4) + (mi << 2)) << 2);
            ldsm4(bv, addr);
            mma8(o[nt], a0, bv[0], bv[1]);
            mma8(o[nt], a1, bv[2], bv[3]);
        }
    }

    // ---- store (reverse cyclic shift +4) ----
    {
        int ohA = ((win_h << 3) + (iA >> 3) + 4) & 63;
        int owA = ((win_w << 3) + (iA & 7) + 4) & 63;
        int ohB = ((win_h << 3) + (iB >> 3) + 4) & 63;
        int owB = ((win_w << 3) + (iB & 7) + 4) & 63;
        float* dA = gout + ((((b << 6) + ohA) << 6) + owA) * 512 + head * 32 + (t4 << 1);
        float* dB = gout + ((((b << 6) + ohB) << 6) + owB) * 512 + head * 32 + (t4 << 1);
        #pragma unroll
        for (int nt = 0; nt < 4; ++nt) {
            *reinterpret_cast<float2*>(dA + (nt << 3)) = make_float2(o[nt][0], o[nt][1]);
            *reinterpret_cast<float2*>(dB + (nt << 3)) = make_float2(o[nt][2], o[nt][3]);
        }
    }
}

}  // namespace

extern "C" void kernel_launch(void* const* d_in, const int* in_sizes, int n_in,
                              void* d_out, int out_size)
{
    (void)in_sizes; (void)n_in; (void)out_size;
    const float* q    = (const float*)d_in[0];
    const float* k    = (const float*)d_in[1];
    const float* v    = (const float*)d_in[2];
    const float* bias = (const float*)d_in[3];
    swin_mma_kernel<<<16384, 128>>>(q, k, v, bias, (float*)d_out);
}

// round 6
// speedup vs baseline: 1.2176x; 1.2176x over previous
#include <cuda_runtime.h>
#include <cstdint>

namespace {

// smem word offsets
constexpr int QH = 0;       // Q hi tf32, stride 36, 64 rows
constexpr int QL = 2304;    // Q lo
constexpr int KH = 4608;    // K hi (no lo: 2xTF32)
constexpr int VO = 6912;    // V row-major [tok][chan], stride 40, 64 rows
constexpr int BI = 9472;    // bias, 225 floats
constexpr int SMW = 9700;   // 38800 bytes
constexpr int PO = 0;       // P overlays QH/QL, stride 68, 64 rows (4352 < 4608)

__device__ __forceinline__ uint32_t cvt_tf32(float x) {
    uint32_t u;
    asm("cvt.rna.tf32.f32 %0, %1;" : "=r"(u) : "f"(x));
    return u;
}
__device__ __forceinline__ uint32_t smem_u32(const void* p) {
    uint32_t a;
    asm("{ .reg .u64 t; cvta.to.shared.u64 t, %1; cvt.u32.u64 %0, t; }" : "=r"(a) : "l"(p));
    return a;
}
__device__ __forceinline__ void mma8(float* c, const uint32_t* a, uint32_t b0, uint32_t b1) {
    asm volatile("mma.sync.aligned.m16n8k8.row.col.f32.tf32.tf32.f32 "
        "{%0,%1,%2,%3}, {%4,%5,%6,%7}, {%8,%9}, {%0,%1,%2,%3};"
        : "+f"(c[0]), "+f"(c[1]), "+f"(c[2]), "+f"(c[3])
        : "r"(a[0]), "r"(a[1]), "r"(a[2]), "r"(a[3]), "r"(b0), "r"(b1));
}
__device__ __forceinline__ void ldsm4(uint32_t* r, uint32_t addr) {
    asm volatile("ldmatrix.sync.aligned.m8n8.x4.shared.b16 {%0,%1,%2,%3}, [%4];"
        : "=r"(r[0]), "=r"(r[1]), "=r"(r[2]), "=r"(r[3]) : "r"(addr));
}

__global__ __launch_bounds__(128, 5)
void swin_mma_kernel(const float* __restrict__ gq, const float* __restrict__ gk,
                     const float* __restrict__ gv, const float* __restrict__ gbias,
                     float* __restrict__ gout)
{
    __shared__ uint32_t SM[SMW];

    const int tid   = threadIdx.x;
    const int head  = blockIdx.x & 15;
    const int wy    = blockIdx.x >> 4;
    const int b     = wy >> 6;
    const int win   = wy & 63;
    const int win_h = win >> 3, win_w = win & 7;
    const float scale = 0.17677669529663687f;   // 1/sqrt(32)

    // ---- load Q,K,V (gather applies cyclic shift -4); Q hi/lo split, K hi, V rowmajor ----
    #pragma unroll
    for (int r = 0; r < 4; ++r) {
        int u = tid + (r << 7);               // 0..511
        int t = u >> 3;                       // token
        int cq = u & 7;                       // channel quad
        int sh  = ((win_h << 3) + (t >> 3) + 4) & 63;
        int sw2 = ((win_w << 3) + (t & 7) + 4) & 63;
        int gbase = ((((b << 6) + sh) << 6) + sw2) * 512 + head * 32 + (cq << 2);
        float4 q = *reinterpret_cast<const float4*>(gq + gbase);
        float4 k = *reinterpret_cast<const float4*>(gk + gbase);
        float4 v = *reinterpret_cast<const float4*>(gv + gbase);
        q.x *= scale; q.y *= scale; q.z *= scale; q.w *= scale;
        uint4 qh, ql, kh, vt;
        qh.x = cvt_tf32(q.x); ql.x = cvt_tf32(q.x - __uint_as_float(qh.x));
        qh.y = cvt_tf32(q.y); ql.y = cvt_tf32(q.y - __uint_as_float(qh.y));
        qh.z = cvt_tf32(q.z); ql.z = cvt_tf32(q.z - __uint_as_float(qh.z));
        qh.w = cvt_tf32(q.w); ql.w = cvt_tf32(q.w - __uint_as_float(qh.w));
        kh.x = cvt_tf32(k.x); kh.y = cvt_tf32(k.y);
        kh.z = cvt_tf32(k.z); kh.w = cvt_tf32(k.w);
        vt.x = cvt_tf32(v.x); vt.y = cvt_tf32(v.y);
        vt.z = cvt_tf32(v.z); vt.w = cvt_tf32(v.w);
        int o36 = t * 36 + (cq << 2);
        *reinterpret_cast<uint4*>(&SM[QH + o36]) = qh;
        *reinterpret_cast<uint4*>(&SM[QL + o36]) = ql;
        *reinterpret_cast<uint4*>(&SM[KH + o36]) = kh;
        *reinterpret_cast<uint4*>(&SM[VO + t * 40 + (cq << 2)]) = vt;
    }
    for (int t = tid; t < 225; t += 128)
        reinterpret_cast<float*>(SM)[BI + t] = gbias[t * 16 + head];
    __syncthreads();

    const int w    = tid >> 5;
    const int lane = tid & 31;
    const int g    = lane >> 2;
    const int t4   = lane & 3;
    const int mi   = lane >> 3;     // matrix index for ldmatrix
    const int l7   = lane & 7;
    const int m0   = w << 4;
    const int iA   = m0 + g;
    const int iB   = m0 + g + 8;

    const uint32_t smb = smem_u32(SM);
    const uint32_t aRow = (uint32_t)(m0 + ((mi & 1) << 3) + l7);
    const uint32_t aQHb = smb + ((QH + aRow * 36 + ((mi >> 1) << 2)) << 2);
    const uint32_t aQLb = aQHb + (uint32_t)((QL - QH) << 2);
    uint32_t bKHb[4];
    #pragma unroll
    for (int m = 0; m < 4; ++m) {
        uint32_t row = (uint32_t)((((m << 1) + (mi >> 1)) << 3) + l7);
        bKHb[m] = smb + ((KH + row * 36 + ((mi & 1) << 2)) << 2);
    }

    // ---- QK: 2xTF32 (qh*kh + ql*kh), LDSM-fed ----
    float c[8][4] = {};
    #pragma unroll
    for (int ks = 0; ks < 4; ++ks) {
        uint32_t ah[4], al[4];
        ldsm4(ah, aQHb + ks * 32u);
        ldsm4(al, aQLb + ks * 32u);
        #pragma unroll
        for (int m = 0; m < 4; ++m) {
            uint32_t bh[4];
            ldsm4(bh, bKHb[m] + ks * 32u);
            float* c0 = c[2 * m];
            float* c1 = c[2 * m + 1];
            mma8(c0, ah, bh[0], bh[1]);
            mma8(c0, al, bh[0], bh[1]);
            mma8(c1, ah, bh[2], bh[3]);
            mma8(c1, al, bh[2], bh[3]);
        }
    }
    __syncthreads();   // Q reads done; QH/QL region free for P overlay

    // ---- epilogue: bias + analytic shift-mask + softmax ----
    const float* bias = reinterpret_cast<const float*>(SM) + BI;
    const bool wh7 = (win_h == 7), ww7 = (win_w == 7);
    const bool hA4 = ((iA >> 3) >= 4), hB4 = ((iB >> 3) >= 4);
    const bool wA4 = ((iA & 7) >= 4),  wB4 = ((iB & 7) >= 4);
    const bool jw4 = (t4 >= 2);
    const int bA = 15 * (iA >> 3) + (iA & 7) + 112;
    const int bB = 15 * (iB >> 3) + (iB & 7) + 112;

    float mA = -1e30f, mB = -1e30f;
    #pragma unroll
    for (int nt = 0; nt < 8; ++nt) {
        const bool jh4 = (nt >= 4);
        const float subA = ((wh7 && (hA4 != jh4)) || (ww7 && (wA4 != jw4))) ? 100.0f : 0.0f;
        const float subB = ((wh7 && (hB4 != jh4)) || (ww7 && (wB4 != jw4))) ? 100.0f : 0.0f;
        #pragma unroll
        for (int q = 0; q < 2; ++q) {
            int bj = 15 * nt + (t4 << 1) + q;
            float xA = c[nt][q]     + bias[bA - bj] - subA;
            float xB = c[nt][2 + q] + bias[bB - bj] - subB;
            c[nt][q] = xA; c[nt][2 + q] = xB;
            mA = fmaxf(mA, xA); mB = fmaxf(mB, xB);
        }
    }
    mA = fmaxf(mA, __shfl_xor_sync(0xffffffffu, mA, 1));
    mA = fmaxf(mA, __shfl_xor_sync(0xffffffffu, mA, 2));
    mB = fmaxf(mB, __shfl_xor_sync(0xffffffffu, mB, 1));
    mB = fmaxf(mB, __shfl_xor_sync(0xffffffffu, mB, 2));
    float sA = 0.0f, sB = 0.0f;
    #pragma unroll
    for (int nt = 0; nt < 8; ++nt) {
        #pragma unroll
        for (int q = 0; q < 2; ++q) {
            float pA = __expf(c[nt][q] - mA);
            float pB = __expf(c[nt][2 + q] - mB);
            c[nt][q] = pA; c[nt][2 + q] = pB;
            sA += pA; sB += pB;
        }
    }
    sA += __shfl_xor_sync(0xffffffffu, sA, 1);
    sA += __shfl_xor_sync(0xffffffffu, sA, 2);
    sB += __shfl_xor_sync(0xffffffffu, sB, 1);
    sB += __shfl_xor_sync(0xffffffffu, sB, 2);
    const float invA = 1.0f / sA, invB = 1.0f / sB;

    // normalized P (tf32) -> smem, stride 68
    #pragma unroll
    for (int nt = 0; nt < 8; ++nt) {
        int jc = (nt << 3) + (t4 << 1);
        uint2 pa, pb;
        pa.x = cvt_tf32(c[nt][0] * invA); pa.y = cvt_tf32(c[nt][1] * invA);
        pb.x = cvt_tf32(c[nt][2] * invB); pb.y = cvt_tf32(c[nt][3] * invB);
        *reinterpret_cast<uint2*>(&SM[PO + iA * 68 + jc]) = pa;
        *reinterpret_cast<uint2*>(&SM[PO + iB * 68 + jc]) = pb;
    }
    __syncwarp();

    // ---- PV: O = P @ V; A via LDSM, B via conflict-free scalar LDS ----
    const uint32_t aPb = smb + ((PO + aRow * 68 + ((mi >> 1) << 2)) << 2);
    float o[4][4] = {};
    #pragma unroll
    for (int ks = 0; ks < 8; ++ks) {
        uint32_t a[4];
        ldsm4(a, aPb + ks * 32u);
        int r0 = VO + ((ks << 3) + t4) * 40 + g;
        int r1 = r0 + 160;                    // +4 rows * stride 40
        #pragma unroll
        for (int nt = 0; nt < 4; ++nt) {
            uint32_t b0 = SM[r0 + (nt << 3)];
            uint32_t b1 = SM[r1 + (nt << 3)];
            mma8(o[nt], a, b0, b1);
        }
    }

    // ---- store (reverse cyclic shift +4) ----
    {
        int ohA = ((win_h << 3) + (iA >> 3) + 4) & 63;
        int owA = ((win_w << 3) + (iA & 7) + 4) & 63;
        int ohB = ((win_h << 3) + (iB >> 3) + 4) & 63;
        int owB = ((win_w << 3) + (iB & 7) + 4) & 63;
        float* dA = gout + ((((b << 6) + ohA) << 6) + owA) * 512 + head * 32 + (t4 << 1);
        float* dB = gout + ((((b << 6) + ohB) << 6) + owB) * 512 + head * 32 + (t4 << 1);
        #pragma unroll
        for (int nt = 0; nt < 4; ++nt) {
            *reinterpret_cast<float2*>(dA + (nt << 3)) = make_float2(o[nt][0], o[nt][1]);
            *reinterpret_cast<float2*>(dB + (nt << 3)) = make_float2(o[nt][2], o[nt][3]);
        }
    }
}

}  // namespace

extern "C" void kernel_launch(void* const* d_in, const int* in_sizes, int n_in,
                              void* d_out, int out_size)
{
    (void)in_sizes; (void)n_in; (void)out_size;
    const float* q    = (const float*)d_in[0];
    const float* k    = (const float*)d_in[1];
    const float* v    = (const float*)d_in[2];
    const float* bias = (const float*)d_in[3];
    swin_mma_kernel<<<16384, 128>>>(q, k, v, bias, (float*)d_out);
}